// round 1
// baseline (speedup 1.0000x reference)
#include <cuda_runtime.h>
#include <math.h>

// Problem constants
#define Bq   64
#define Lq   256
#define DINq 768
#define Hq   64
#define Eq   8
#define NT   (Bq * Lq)   // 16384 tokens

// ---------------- device scratch (static allocation, allowed) ----------------
__device__ float g_mean[NT];                 // dte.mean(-1)
__device__ int   g_e1[Bq], g_e2[Bq];
__device__ float g_g1[Bq], g_g2[Bq];
__device__ float g_gbias[Bq * Hq];           // gates @ b_exp
__device__ float g_Wcomb[Bq * DINq * Hq];    // per-b combined expert weight (12.6MB)
__device__ float g_Y  [NT * Hq];             // y
__device__ float g_SH [NT * Hq];             // sh = dte@W_sh + b_sh (pre-LN, shortcut)
__device__ float g_RGB[NT * Hq];             // rgb_tok
__device__ float g_T  [NT * 2 * Hq];         // t1|t2 after W_px

// ---------------- small helpers ----------------
__device__ __forceinline__ float gelu1(float x) {
    return 0.5f * x * (1.0f + erff(x * 0.7071067811865475f));
}
__device__ __forceinline__ float4 f4add(float4 a, float4 b) {
    return make_float4(a.x + b.x, a.y + b.y, a.z + b.z, a.w + b.w);
}
__device__ __forceinline__ float4 f4mul(float4 a, float4 b) {
    return make_float4(a.x * b.x, a.y * b.y, a.z * b.z, a.w * b.w);
}
__device__ __forceinline__ float4 gelu4(float4 a) {
    return make_float4(gelu1(a.x), gelu1(a.y), gelu1(a.z), gelu1(a.w));
}

// ---------------- K0: row mean of dte over DIN ----------------
__global__ void k_mean(const float* __restrict__ dte) {
    int w = threadIdx.x >> 5, lane = threadIdx.x & 31;
    int row = blockIdx.x * 8 + w;
    const float* p = dte + (size_t)row * DINq + lane;
    float s = 0.0f;
#pragma unroll
    for (int k = 0; k < DINq / 32; k++) s += p[k * 32];
#pragma unroll
    for (int o = 16; o; o >>= 1) s += __shfl_xor_sync(0xffffffffu, s, o);
    if (lane == 0) g_mean[row] = s * (1.0f / (float)DINq);
}

// ---------------- K1: gating (logits, top-2, gates, bias, loss) ----------------
__global__ void k_gate(const float* __restrict__ w_gate,
                       const float* __restrict__ b_exp,
                       float* __restrict__ d_out, int loss_idx) {
    __shared__ float s_imp[Eq];
    __shared__ float s_load[Eq];
    int b = threadIdx.x;   // blockDim = 64
    if (b < Eq) { s_imp[b] = 0.0f; s_load[b] = 0.0f; }
    __syncthreads();

    float lg[Eq];
#pragma unroll
    for (int e = 0; e < Eq; e++) lg[e] = 0.0f;
    for (int l = 0; l < Lq; l++) {
        float m = g_mean[b * Lq + l];
#pragma unroll
        for (int e = 0; e < Eq; e++) lg[e] += m * w_gate[l * Eq + e];
    }
    // top-2 (ties -> lowest index, matching lax.top_k)
    int e1 = 0;
    for (int e = 1; e < Eq; e++) if (lg[e] > lg[e1]) e1 = e;
    int e2 = -1;
    for (int e = 0; e < Eq; e++) {
        if (e == e1) continue;
        if (e2 < 0 || lg[e] > lg[e2]) e2 = e;
    }
    float v1 = lg[e1], v2 = lg[e2];
    float ex = expf(v2 - v1);
    float den = 1.0f / (1.0f + ex);
    float g1 = den, g2 = ex * den;

    g_e1[b] = e1; g_e2[b] = e2; g_g1[b] = g1; g_g2[b] = g2;
    for (int h = 0; h < Hq; h++)
        g_gbias[b * Hq + h] = g1 * b_exp[e1 * Hq + h] + g2 * b_exp[e2 * Hq + h];

    atomicAdd(&s_imp[e1], g1);
    atomicAdd(&s_imp[e2], g2);
    atomicAdd(&s_load[e1], 1.0f);
    atomicAdd(&s_load[e2], 1.0f);
    __syncthreads();

    if (b == 0) {
        float m1 = 0.0f, m2 = 0.0f;
        for (int e = 0; e < Eq; e++) { m1 += s_imp[e]; m2 += s_load[e]; }
        m1 *= (1.0f / Eq); m2 *= (1.0f / Eq);
        float var1 = 0.0f, var2 = 0.0f;
        for (int e = 0; e < Eq; e++) {
            float d1 = s_imp[e] - m1;  var1 += d1 * d1;
            float d2 = s_load[e] - m2; var2 += d2 * d2;
        }
        var1 *= (1.0f / (Eq - 1)); var2 *= (1.0f / (Eq - 1));
        float cv1 = var1 / (m1 * m1 + 1e-10f);
        float cv2 = var2 / (m2 * m2 + 1e-10f);
        d_out[loss_idx] = 0.01f * (cv1 + cv2);
    }
}

// ---------------- K2: combined expert weight ----------------
__global__ void k_wcomb(const float* __restrict__ W_exp) {
    int b = blockIdx.y;
    int idx = blockIdx.x * 256 + threadIdx.x;       // < 12288 float4s
    float g1 = g_g1[b], g2 = g_g2[b];
    int e1 = g_e1[b], e2 = g_e2[b];
    const float4* w1 = (const float4*)W_exp + (size_t)e1 * (DINq * Hq / 4);
    const float4* w2 = (const float4*)W_exp + (size_t)e2 * (DINq * Hq / 4);
    float4 a = w1[idx], c = w2[idx];
    float4 r = make_float4(g1 * a.x + g2 * c.x, g1 * a.y + g2 * c.y,
                           g1 * a.z + g2 * c.z, g1 * a.w + g2 * c.w);
    ((float4*)g_Wcomb)[(size_t)b * (DINq * Hq / 4) + idx] = r;
}

// ---------------- K3: tiled GEMM, C[M,64] = A[M,768] @ W[768,64] + bias ----------------
// Batched via blockIdx.z with element strides (0 for shared operands).
__global__ void __launch_bounds__(256) k_gemm768(
    const float* __restrict__ A, size_t aS,
    const float* __restrict__ W, size_t wS,
    const float* __restrict__ bias, size_t bS,
    float* __restrict__ C, size_t cS) {
    __shared__ float As[32][68];   // [k][m], padded so rows stay 16B aligned
    __shared__ float Bs[32][64];   // [k][n]
    int z = blockIdx.z;
    const float* Ab = A + z * aS + (size_t)blockIdx.x * 64 * DINq;
    const float* Wb = W + z * wS;
    const float* bb = bias + z * bS;
    float* Cb = C + z * cS + (size_t)blockIdx.x * 64 * 64;

    int tid = threadIdx.x;
    int tx = tid & 15, ty = tid >> 4;
    float acc[4][4];
#pragma unroll
    for (int i = 0; i < 4; i++)
#pragma unroll
        for (int j = 0; j < 4; j++) acc[i][j] = 0.0f;

    for (int k0 = 0; k0 < DINq; k0 += 32) {
#pragma unroll
        for (int i = 0; i < 2; i++) {
            int idx = tid * 2 + i;
            int r = idx >> 3, kq = idx & 7;
            float4 v = *(const float4*)(Ab + (size_t)r * DINq + k0 + kq * 4);
            As[kq * 4 + 0][r] = v.x;
            As[kq * 4 + 1][r] = v.y;
            As[kq * 4 + 2][r] = v.z;
            As[kq * 4 + 3][r] = v.w;
            int r2 = idx >> 4, nq = idx & 15;
            float4 w = *(const float4*)(Wb + (size_t)(k0 + r2) * 64 + nq * 4);
            *(float4*)&Bs[r2][nq * 4] = w;
        }
        __syncthreads();
#pragma unroll
        for (int k = 0; k < 32; k++) {
            float a0[4], b0[4];
            *(float4*)a0 = *(const float4*)&As[k][ty * 4];
            *(float4*)b0 = *(const float4*)&Bs[k][tx * 4];
#pragma unroll
            for (int i = 0; i < 4; i++)
#pragma unroll
                for (int j = 0; j < 4; j++) acc[i][j] += a0[i] * b0[j];
        }
        __syncthreads();
    }
#pragma unroll
    for (int i = 0; i < 4; i++) {
        int row = ty * 4 + i;
        float4 o = make_float4(acc[i][0] + bb[tx * 4 + 0],
                               acc[i][1] + bb[tx * 4 + 1],
                               acc[i][2] + bb[tx * 4 + 2],
                               acc[i][3] + bb[tx * 4 + 3]);
        *(float4*)(Cb + (size_t)row * 64 + tx * 4) = o;
    }
}

// ---------------- K4: LayerNorm + W_px -> T (t1|t2) ----------------
__global__ void __launch_bounds__(128) k_preln(
    const float* __restrict__ W_px, const float* __restrict__ b_px,
    const float* __restrict__ ln_g, const float* __restrict__ ln_b) {
    extern __shared__ float sm[];
    float* s_w = sm;             // 8192  (W_px, row-major [64][128])
    float* s_g = sm + 8192;      // 64
    float* s_b = sm + 8256;      // 64
    float* s_t = sm + 8320;      // 128 * 68 normalized rows

    int tid = threadIdx.x;
    for (int i = tid; i < 2048; i += 128)
        ((float4*)s_w)[i] = ((const float4*)W_px)[i];
    if (tid < 64) { s_g[tid] = ln_g[tid]; s_b[tid] = ln_b[tid]; }

    int t = blockIdx.x * 128 + tid;
    const float* sh = g_SH + (size_t)t * Hq;
    float mean = 0.0f;
    for (int h = 0; h < Hq; h++) mean += sh[h];
    mean *= (1.0f / Hq);
    float var = 0.0f;
    for (int h = 0; h < Hq; h++) { float d = sh[h] - mean; var += d * d; }
    var *= (1.0f / Hq);
    float rstd = rsqrtf(var + 1e-6f);
    __syncthreads();

    float* tr = s_t + tid * 68;
    for (int h = 0; h < Hq; h++)
        tr[h] = (sh[h] - mean) * rstd * s_g[h] + s_b[h];

    float* outp = g_T + (size_t)t * 128;
    const float4* w4 = (const float4*)s_w;   // [h][32]
    for (int jq = 0; jq < 32; jq++) {
        float4 acc = __ldg((const float4*)b_px + jq);
#pragma unroll 4
        for (int h4 = 0; h4 < 16; h4++) {
            float4 iv = *(const float4*)(tr + h4 * 4);
            float4 w;
            w = w4[(h4 * 4 + 0) * 32 + jq];
            acc.x += iv.x * w.x; acc.y += iv.x * w.y; acc.z += iv.x * w.z; acc.w += iv.x * w.w;
            w = w4[(h4 * 4 + 1) * 32 + jq];
            acc.x += iv.y * w.x; acc.y += iv.y * w.y; acc.z += iv.y * w.z; acc.w += iv.y * w.w;
            w = w4[(h4 * 4 + 2) * 32 + jq];
            acc.x += iv.z * w.x; acc.y += iv.z * w.y; acc.z += iv.z * w.z; acc.w += iv.z * w.w;
            w = w4[(h4 * 4 + 3) * 32 + jq];
            acc.x += iv.w * w.x; acc.y += iv.w * w.y; acc.z += iv.w * w.z; acc.w += iv.w * w.w;
        }
        ((float4*)outp)[jq] = acc;
    }
}

// ---------------- 64x64 row-matmul helper: out4 = sum_h in[h] * W[h][4jq..] ----------------
__device__ __forceinline__ float4 mm_row(const float* __restrict__ in,
                                         const float* __restrict__ wsm, int jq) {
    const float4* w4 = (const float4*)wsm;   // [h][16]
    float4 acc = make_float4(0.f, 0.f, 0.f, 0.f);
#pragma unroll 4
    for (int h4 = 0; h4 < 16; h4++) {
        float4 iv = *(const float4*)(in + h4 * 4);
        float4 w;
        w = w4[(h4 * 4 + 0) * 16 + jq];
        acc.x += iv.x * w.x; acc.y += iv.x * w.y; acc.z += iv.x * w.z; acc.w += iv.x * w.w;
        w = w4[(h4 * 4 + 1) * 16 + jq];
        acc.x += iv.y * w.x; acc.y += iv.y * w.y; acc.z += iv.y * w.z; acc.w += iv.y * w.w;
        w = w4[(h4 * 4 + 2) * 16 + jq];
        acc.x += iv.z * w.x; acc.y += iv.z * w.y; acc.z += iv.z * w.z; acc.w += iv.z * w.w;
        w = w4[(h4 * 4 + 3) * 16 + jq];
        acc.x += iv.w * w.x; acc.y += iv.w * w.y; acc.z += iv.w * w.z; acc.w += iv.w * w.w;
    }
    return acc;
}

// ---------------- K5: conv + GLU + remaining 64x64 matmul chain ----------------
__global__ void __launch_bounds__(128) k_post(
    const float* __restrict__ conv_sh,
    const float* __restrict__ W_pxx,    const float* __restrict__ b_pxx,
    const float* __restrict__ W_dte,    const float* __restrict__ b_dte,
    const float* __restrict__ W_dteall, const float* __restrict__ b_dteall,
    const float* __restrict__ W_fmod,   const float* __restrict__ b_fmod,
    const float* __restrict__ W_fx,     const float* __restrict__ b_fx,
    const float* __restrict__ W_fxx,    const float* __restrict__ b_fxx,
    float* __restrict__ d_out) {
    extern __shared__ float sm[];
    // layout: 6 weights (4096 each), convT (576), sA/sB/sC rows (128*68 each)
    float* s_pxx    = sm;
    float* s_dte    = sm + 4096;
    float* s_dteall = sm + 8192;
    float* s_fmod   = sm + 12288;
    float* s_fx     = sm + 16384;
    float* s_fxx    = sm + 20480;
    float* s_cv     = sm + 24576;            // [tap][h]
    float* sA       = sm + 25152;
    float* sB       = sm + 25152 + 8704;
    float* sC       = sm + 25152 + 2 * 8704;

    int tid = threadIdx.x;
    {
        const float* wsrc[6] = {W_pxx, W_dte, W_dteall, W_fmod, W_fx, W_fxx};
#pragma unroll
        for (int m = 0; m < 6; m++)
            for (int i = tid; i < 1024; i += 128)
                ((float4*)(sm + m * 4096))[i] = ((const float4*)wsrc[m])[i];
        for (int i = tid; i < 576; i += 128) {
            int tap = i >> 6, h = i & 63;
            s_cv[i] = conv_sh[h * 9 + tap];
        }
    }
    __syncthreads();

    int t = blockIdx.x * 128 + tid;
    int l = t & 255, ii = l >> 4, jj = l & 15;
    float* rA = sA + tid * 68;
    float* rB = sB + tid * 68;
    float* rC = sC + tid * 68;
    const float* Trow = g_T + (size_t)t * 128;

    // gated = gelu(conv(t1)) * t2  -> rA
    for (int q = 0; q < 16; q++) {
        float4 acc = make_float4(0.f, 0.f, 0.f, 0.f);
#pragma unroll
        for (int tap = 0; tap < 9; tap++) {
            int di = tap / 3 - 1, dj = tap % 3 - 1;
            int ni = ii + di, nj = jj + dj;
            if (ni < 0 || ni > 15 || nj < 0 || nj > 15) continue;
            float4 v = *(const float4*)(g_T + (size_t)(t + di * 16 + dj) * 128 + q * 4);
            float4 w = *(const float4*)(s_cv + tap * 64 + q * 4);
            acc = f4add(acc, f4mul(v, w));
        }
        float4 t2 = *(const float4*)(Trow + 64 + q * 4);
        *(float4*)(rA + q * 4) = f4mul(gelu4(acc), t2);
    }

    // sh_new = gated @ W_pxx + b_pxx + SH -> rB
    for (int q = 0; q < 16; q++) {
        float4 acc = mm_row(rA, s_pxx, q);
        acc = f4add(acc, __ldg((const float4*)b_pxx + q));
        acc = f4add(acc, *(const float4*)(g_SH + (size_t)t * 64 + q * 4));
        *(float4*)(rB + q * 4) = acc;
    }

    // Y row -> rC
    for (int q = 0; q < 16; q++)
        *(float4*)(rC + q * 4) = *(const float4*)(g_Y + (size_t)t * 64 + q * 4);

    // dte_tok = Y@W_dte + b_dte + sh_new@W_dteall + b_dteall ; gelu -> rA
    for (int q = 0; q < 16; q++) {
        float4 acc = mm_row(rC, s_dte, q);
        acc = f4add(acc, mm_row(rB, s_dteall, q));
        acc = f4add(acc, __ldg((const float4*)b_dte + q));
        acc = f4add(acc, __ldg((const float4*)b_dteall + q));
        *(float4*)(rA + q * 4) = gelu4(acc);
    }

    // m = gelu(dte_tok)@W_fmod + b_fmod ; gelu -> rB
    for (int q = 0; q < 16; q++) {
        float4 acc = mm_row(rA, s_fmod, q);
        acc = f4add(acc, __ldg((const float4*)b_fmod + q));
        *(float4*)(rB + q * 4) = gelu4(acc);
    }

    // gelu(rgb) -> rC
    for (int q = 0; q < 16; q++)
        *(float4*)(rC + q * 4) =
            gelu4(*(const float4*)(g_RGB + (size_t)t * 64 + q * 4));

    // a = gelu(rgb)@W_fx + b_fx ; g = gelu(m) * a -> rB
    for (int q = 0; q < 16; q++) {
        float4 a = mm_row(rC, s_fx, q);
        a = f4add(a, __ldg((const float4*)b_fx + q));
        float4 gm = *(const float4*)(rB + q * 4);
        *(float4*)(rB + q * 4) = f4mul(gm, a);
    }

    // out = g@W_fxx + b_fxx + rgb
    for (int q = 0; q < 16; q++) {
        float4 acc = mm_row(rB, s_fxx, q);
        acc = f4add(acc, __ldg((const float4*)b_fxx + q));
        acc = f4add(acc, *(const float4*)(g_RGB + (size_t)t * 64 + q * 4));
        *(float4*)(d_out + (size_t)t * 64 + q * 4) = acc;
    }
}

// ---------------- host launcher ----------------
extern "C" void kernel_launch(void* const* d_in, const int* in_sizes, int n_in,
                              void* d_out, int out_size) {
    const float* x        = (const float*)d_in[0];
    const float* dte      = (const float*)d_in[1];
    const float* w_gate   = (const float*)d_in[2];
    const float* W_exp    = (const float*)d_in[3];
    const float* b_exp    = (const float*)d_in[4];
    const float* W_sh     = (const float*)d_in[5];
    const float* b_sh     = (const float*)d_in[6];
    const float* ln_g     = (const float*)d_in[7];
    const float* ln_b     = (const float*)d_in[8];
    const float* W_px     = (const float*)d_in[9];
    const float* b_px     = (const float*)d_in[10];
    const float* conv_sh  = (const float*)d_in[11];
    const float* W_pxx    = (const float*)d_in[12];
    const float* b_pxx    = (const float*)d_in[13];
    const float* W_dte    = (const float*)d_in[14];
    const float* b_dte    = (const float*)d_in[15];
    const float* W_dteall = (const float*)d_in[16];
    const float* b_dteall = (const float*)d_in[17];
    const float* W_rgb    = (const float*)d_in[18];
    const float* b_rgb    = (const float*)d_in[19];
    const float* W_fx     = (const float*)d_in[20];
    const float* b_fx     = (const float*)d_in[21];
    const float* W_fmod   = (const float*)d_in[22];
    const float* b_fmod   = (const float*)d_in[23];
    const float* W_fxx    = (const float*)d_in[24];
    const float* b_fxx    = (const float*)d_in[25];
    float* out = (float*)d_out;

    void *p_wcomb, *p_gbias, *p_Y, *p_SH, *p_RGB;
    cudaGetSymbolAddress(&p_wcomb, g_Wcomb);
    cudaGetSymbolAddress(&p_gbias, g_gbias);
    cudaGetSymbolAddress(&p_Y, g_Y);
    cudaGetSymbolAddress(&p_SH, g_SH);
    cudaGetSymbolAddress(&p_RGB, g_RGB);

    cudaFuncSetAttribute(k_preln, cudaFuncAttributeMaxDynamicSharedMemorySize, 68096);
    cudaFuncSetAttribute(k_post,  cudaFuncAttributeMaxDynamicSharedMemorySize, 205056);

    // gating path
    k_mean<<<NT / 8, 256>>>(dte);
    k_gate<<<1, 64>>>(w_gate, b_exp, out, out_size - 1);
    k_wcomb<<<dim3(48, Bq), 256>>>(W_exp);

    // big GEMMs
    k_gemm768<<<dim3(4, 1, Bq), 256>>>(dte, (size_t)Lq * DINq,
                                       (const float*)p_wcomb, (size_t)DINq * Hq,
                                       (const float*)p_gbias, (size_t)Hq,
                                       (float*)p_Y, (size_t)Lq * Hq);
    k_gemm768<<<dim3(256, 1, 1), 256>>>(dte, 0, W_sh, 0, b_sh, 0,
                                        (float*)p_SH, 0);
    k_gemm768<<<dim3(256, 1, 1), 256>>>(x, 0, W_rgb, 0, b_rgb, 0,
                                        (float*)p_RGB, 0);

    // token chain
    k_preln<<<128, 128, 68096>>>(W_px, b_px, ln_g, ln_b);
    k_post<<<128, 128, 205056>>>(conv_sh,
                                 W_pxx, b_pxx, W_dte, b_dte, W_dteall, b_dteall,
                                 W_fmod, b_fmod, W_fx, b_fx, W_fxx, b_fxx,
                                 out);
}